// round 1
// baseline (speedup 1.0000x reference)
#include <cuda_runtime.h>
#include <cuda_bf16.h>
#include <math.h>

#define N_NODES 100000
#define N_EDGES 1600000
#define D_IN 64
#define D_OUT 64
#define D_EDGE 16

// ---------------- scratch (device globals; no allocation) ----------------
__device__ float g_u[80];                    // W1^T @ att_l (first 64 for x, last 16 for edge_attr)
__device__ float g_xt[N_NODES * D_OUT];      // x @ W2^T
__device__ float g_al[N_NODES];              // x . u[0:64]
__device__ float g_ar[N_NODES];              // x . att_r
__device__ float g_denom[N_NODES];           // sum of exp per dst
__device__ float g_hraw[N_NODES * D_OUT];    // sum of x_t[src]*exp per dst

// ---------------- K0: zero scratch ----------------
__global__ void k_init() {
    long long total = (long long)N_NODES * D_OUT + N_NODES;
    for (long long i = (long long)blockIdx.x * blockDim.x + threadIdx.x; i < total;
         i += (long long)gridDim.x * blockDim.x) {
        if (i < (long long)N_NODES * D_OUT) g_hraw[i] = 0.0f;
        else g_denom[i - (long long)N_NODES * D_OUT] = 0.0f;
    }
}

// ---------------- K1: u[c] = sum_o att_l[o] * W1[o][c],  W1 is [64,80] ----------------
__global__ void k_u(const float* __restrict__ W1, const float* __restrict__ att_l) {
    int c = threadIdx.x;
    if (c < 80) {
        float acc = 0.0f;
        #pragma unroll
        for (int o = 0; o < D_OUT; o++) acc += att_l[o] * W1[o * 80 + c];
        g_u[c] = acc;
    }
}

// ---------------- K2: per-node transform ----------------
// x_t[n][j] = sum_k x[n][k] * W2[j][k];  al[n] = x[n].u1;  ar[n] = x[n].att_r
__global__ void k_node(const float* __restrict__ x, const float* __restrict__ W2,
                       const float* __restrict__ att_r) {
    __shared__ float w2t[D_IN * D_OUT];   // transposed: w2t[k*64+j] = W2[j][k]
    __shared__ float xs[4 * D_IN];
    int tid = threadIdx.x;
    for (int i = tid; i < D_IN * D_OUT; i += 256) {
        int j = i >> 6, k = i & 63;
        w2t[(k << 6) | j] = W2[i];
    }
    __syncthreads();

    int ln = tid >> 6;       // local node 0..3
    int j  = tid & 63;       // output dim

    for (int tile = blockIdx.x; tile * 4 < N_NODES; tile += gridDim.x) {
        int node0 = tile * 4;
        __syncthreads();
        int gi = node0 * D_IN + tid;
        xs[tid] = (gi < N_NODES * D_IN) ? x[gi] : 0.0f;
        __syncthreads();

        int n = node0 + ln;
        if (n < N_NODES) {
            float acc = 0.0f;
            #pragma unroll
            for (int k = 0; k < D_IN; k++) acc += xs[(ln << 6) + k] * w2t[(k << 6) + j];
            g_xt[n * D_OUT + j] = acc;
            if (j == 0) {
                float a = 0.0f, r = 0.0f;
                #pragma unroll
                for (int k = 0; k < D_IN; k++) {
                    float xv = xs[(ln << 6) + k];
                    a += xv * g_u[k];
                    r += xv * att_r[k];
                }
                g_al[n] = a;
                g_ar[n] = r;
            }
        }
    }
}

// ---------------- K3: per-edge (warp per edge) ----------------
__global__ void k_edge(const float* __restrict__ edge_attr,
                       const int* __restrict__ src, const int* __restrict__ dst) {
    int gw = (blockIdx.x * blockDim.x + threadIdx.x) >> 5;  // edge id
    if (gw >= N_EDGES) return;
    int lane = threadIdx.x & 31;

    int s = __ldg(&src[gw]);
    int d = __ldg(&dst[gw]);

    float p = 0.0f;
    if (lane < D_EDGE) p = edge_attr[gw * D_EDGE + lane] * g_u[D_IN + lane];
    #pragma unroll
    for (int off = 16; off; off >>= 1) p += __shfl_xor_sync(0xFFFFFFFFu, p, off);

    float ee = g_al[s] + g_ar[d] + p;
    ee = (ee > 0.0f) ? ee : 0.01f * ee;      // leaky relu
    float ex = expf(ee);                      // no max-shift needed (|e| small)

    if (lane == 0) atomicAdd(&g_denom[d], ex);

    if (lane < 16) {
        const float4 v = *reinterpret_cast<const float4*>(&g_xt[s * D_OUT + lane * 4]);
        float m0 = v.x * ex, m1 = v.y * ex, m2 = v.z * ex, m3 = v.w * ex;
        unsigned long long addr =
            __cvta_generic_to_global(&g_hraw[d * D_OUT + lane * 4]);
        asm volatile("red.global.add.v4.f32 [%0], {%1, %2, %3, %4};"
                     :: "l"(addr), "f"(m0), "f"(m1), "f"(m2), "f"(m3)
                     : "memory");
    }
}

// ---------------- K4: per-node finalize (warp per node): normalize + bias + LayerNorm ----------------
__global__ void k_final(const float* __restrict__ bias, const float* __restrict__ gamma,
                        const float* __restrict__ beta, float* __restrict__ out) {
    int n = (blockIdx.x * blockDim.x + threadIdx.x) >> 5;
    if (n >= N_NODES) return;
    int lane = threadIdx.x & 31;

    float dnm = g_denom[n];
    float inv = (dnm > 0.0f) ? (1.0f / dnm) : 0.0f;

    float a = g_hraw[n * D_OUT + lane]       * inv + bias[lane];
    float b = g_hraw[n * D_OUT + lane + 32]  * inv + bias[lane + 32];

    float sm = a + b;
    #pragma unroll
    for (int off = 16; off; off >>= 1) sm += __shfl_xor_sync(0xFFFFFFFFu, sm, off);
    float mu = sm * (1.0f / 64.0f);

    float da = a - mu, db = b - mu;
    float vs = da * da + db * db;
    #pragma unroll
    for (int off = 16; off; off >>= 1) vs += __shfl_xor_sync(0xFFFFFFFFu, vs, off);
    float rstd = rsqrtf(vs * (1.0f / 64.0f) + 1e-5f);

    out[n * D_OUT + lane]      = da * rstd * gamma[lane]      + beta[lane];
    out[n * D_OUT + lane + 32] = db * rstd * gamma[lane + 32] + beta[lane + 32];
}

// ---------------- launch ----------------
extern "C" void kernel_launch(void* const* d_in, const int* in_sizes, int n_in,
                              void* d_out, int out_size) {
    const float* x         = (const float*)d_in[0];
    const float* edge_attr = (const float*)d_in[1];
    const float* W1        = (const float*)d_in[2];
    const float* W2        = (const float*)d_in[3];
    const float* att_l     = (const float*)d_in[4];
    const float* att_r     = (const float*)d_in[5];
    const float* bias      = (const float*)d_in[6];
    const float* ln_gamma  = (const float*)d_in[7];
    const float* ln_beta   = (const float*)d_in[8];
    const int*   src       = (const int*)d_in[9];
    const int*   dst       = (const int*)d_in[10];
    float* out = (float*)d_out;

    k_init<<<8192, 256>>>();
    k_u<<<1, 80>>>(W1, att_l);
    k_node<<<2048, 256>>>(x, W2, att_r);
    k_edge<<<(N_EDGES * 32 + 255) / 256, 256>>>(edge_attr, src, dst);
    k_final<<<(N_NODES * 32 + 255) / 256, 256>>>(bias, ln_gamma, ln_beta, out);
}

// round 2
// speedup vs baseline: 2.1788x; 2.1788x over previous
#include <cuda_runtime.h>
#include <cuda_bf16.h>
#include <math.h>

#define N_NODES 100000
#define N_EDGES 1600000
#define D_IN 64
#define D_OUT 64
#define D_EDGE 16
#define NBLK_SCAN ((N_NODES + 255) / 256)   // 391

// ---------------- scratch (device globals; no allocation) ----------------
__device__ float g_u[80];                         // W1^T @ att_l
__device__ float g_al[N_NODES];                   // x . u[0:64]
__device__ float g_ar[N_NODES];                   // x . att_r
__device__ float g_ex[N_EDGES];                   // exp(leaky(e))
__device__ int   g_cnt[N_NODES];                  // in-degree
__device__ int   g_off[N_NODES];                  // CSR offsets (exclusive scan)
__device__ int   g_cursor[N_NODES];               // scatter cursors
__device__ int   g_bsum[NBLK_SCAN];               // scan block sums
__device__ int   g_bscan[NBLK_SCAN];              // scanned block sums
__device__ unsigned long long g_cedge[N_EDGES];   // packed (ex<<32 | src)

// ---------------- K1: u[c] = sum_o att_l[o] * W1[o][c] ----------------
__global__ void k_u(const float* __restrict__ W1, const float* __restrict__ att_l) {
    int c = threadIdx.x;
    if (c < 80) {
        float acc = 0.0f;
        #pragma unroll
        for (int o = 0; o < D_OUT; o++) acc += att_l[o] * W1[o * 80 + c];
        g_u[c] = acc;
    }
}

// ---------------- K2: warp-per-node al/ar + zero histogram ----------------
__global__ void k_pre(const float* __restrict__ x, const float* __restrict__ att_r) {
    int n = (blockIdx.x * blockDim.x + threadIdx.x) >> 5;
    if (n >= N_NODES) return;
    int lane = threadIdx.x & 31;

    float x0 = x[n * 64 + lane];
    float x1 = x[n * 64 + 32 + lane];
    float pa = x0 * g_u[lane] + x1 * g_u[lane + 32];
    float pr = x0 * att_r[lane] + x1 * att_r[lane + 32];
    #pragma unroll
    for (int off = 16; off; off >>= 1) {
        pa += __shfl_xor_sync(0xFFFFFFFFu, pa, off);
        pr += __shfl_xor_sync(0xFFFFFFFFu, pr, off);
    }
    if (lane == 0) {
        g_al[n] = pa;
        g_ar[n] = pr;
        g_cnt[n] = 0;
    }
}

// ---------------- K3: thread-per-edge score + histogram ----------------
__global__ void k_edgepre(const float* __restrict__ edge_attr,
                          const int* __restrict__ src, const int* __restrict__ dst) {
    __shared__ float su[16];
    if (threadIdx.x < 16) su[threadIdx.x] = g_u[64 + threadIdx.x];
    __syncthreads();

    int e = blockIdx.x * blockDim.x + threadIdx.x;
    if (e >= N_EDGES) return;

    const float4* ea = reinterpret_cast<const float4*>(edge_attr) + e * 4;
    float p = 0.0f;
    #pragma unroll
    for (int q = 0; q < 4; q++) {
        float4 v = ea[q];
        p += v.x * su[q * 4 + 0] + v.y * su[q * 4 + 1]
           + v.z * su[q * 4 + 2] + v.w * su[q * 4 + 3];
    }
    int s = src[e], d = dst[e];
    float ee = g_al[s] + g_ar[d] + p;
    ee = (ee > 0.0f) ? ee : 0.01f * ee;
    g_ex[e] = __expf(ee) ;
    atomicAdd(&g_cnt[d], 1);
}

// ---------------- K4a/b/c: exclusive scan of g_cnt -> g_off, g_cursor ----------------
__global__ void k_scan_a() {
    int tid = threadIdx.x, lane = tid & 31, wid = tid >> 5;
    int i = blockIdx.x * 256 + tid;
    int v = (i < N_NODES) ? g_cnt[i] : 0;
    int inc = v;
    #pragma unroll
    for (int d = 1; d < 32; d <<= 1) {
        int t = __shfl_up_sync(0xFFFFFFFFu, inc, d);
        if (lane >= d) inc += t;
    }
    __shared__ int wsum[8];
    if (lane == 31) wsum[wid] = inc;
    __syncthreads();
    if (tid < 8) {
        int w = wsum[tid];
        #pragma unroll
        for (int d = 1; d < 8; d <<= 1) {
            int t = __shfl_up_sync(0xFFu, w, d);
            if (tid >= d) w += t;
        }
        wsum[tid] = w;
    }
    __syncthreads();
    int base = (wid > 0) ? wsum[wid - 1] : 0;
    if (i < N_NODES) g_off[i] = base + inc - v;
    if (tid == 0) g_bsum[blockIdx.x] = wsum[7];
}

__global__ void k_scan_b() {
    int tid = threadIdx.x, lane = tid & 31, wid = tid >> 5;
    int v = (tid < NBLK_SCAN) ? g_bsum[tid] : 0;
    int inc = v;
    #pragma unroll
    for (int d = 1; d < 32; d <<= 1) {
        int t = __shfl_up_sync(0xFFFFFFFFu, inc, d);
        if (lane >= d) inc += t;
    }
    __shared__ int wsum[16];
    if (lane == 31) wsum[wid] = inc;
    __syncthreads();
    if (tid < 16) {
        int w = wsum[tid];
        #pragma unroll
        for (int d = 1; d < 16; d <<= 1) {
            int t = __shfl_up_sync(0xFFFFu, w, d);
            if (tid >= d) w += t;
        }
        wsum[tid] = w;
    }
    __syncthreads();
    int base = (wid > 0) ? wsum[wid - 1] : 0;
    if (tid < NBLK_SCAN) g_bscan[tid] = base + inc - v;
}

__global__ void k_scan_c() {
    int i = blockIdx.x * blockDim.x + threadIdx.x;
    if (i < N_NODES) {
        int o = g_off[i] + g_bscan[i >> 8];
        g_off[i] = o;
        g_cursor[i] = o;
    }
}

// ---------------- K5: scatter packed (ex, src) into CSR ----------------
__global__ void k_scatter(const int* __restrict__ src, const int* __restrict__ dst) {
    int e = blockIdx.x * blockDim.x + threadIdx.x;
    if (e >= N_EDGES) return;
    int d = dst[e];
    int pos = atomicAdd(&g_cursor[d], 1);
    unsigned long long pk =
        ((unsigned long long)__float_as_uint(g_ex[e]) << 32) | (unsigned)src[e];
    g_cedge[pos] = pk;
}

// ---------------- K6: warp-per-dst aggregate + W2 GEMM + bias + LayerNorm ----------------
__global__ void k_agg(const float* __restrict__ x, const float* __restrict__ W2,
                      const float* __restrict__ bias, const float* __restrict__ gamma,
                      const float* __restrict__ beta, float* __restrict__ out) {
    __shared__ float w2t[64 * 65];   // w2t[k*65+j] = W2[j][k], padded: conflict-free
    int tid = threadIdx.x;
    for (int i = tid; i < 64 * 64; i += 256) {
        int j = i >> 6, k = i & 63;
        w2t[k * 65 + j] = W2[i];
    }
    __syncthreads();

    int lane = tid & 31, wid = tid >> 5;

    for (int n = blockIdx.x * 8 + wid; n < N_NODES; n += gridDim.x * 8) {
        int start = g_off[n];
        int cnt = g_cnt[n];
        float acc0 = 0.0f, acc1 = 0.0f, den = 0.0f;

        int i = 0;
        for (; i + 1 < cnt; i += 2) {
            unsigned long long p0 = g_cedge[start + i];
            unsigned long long p1 = g_cedge[start + i + 1];
            int s0 = (int)(p0 & 0xFFFFFFFFu);
            int s1 = (int)(p1 & 0xFFFFFFFFu);
            float e0 = __uint_as_float((unsigned)(p0 >> 32));
            float e1 = __uint_as_float((unsigned)(p1 >> 32));
            float a0 = __ldg(&x[s0 * 64 + lane]);
            float b0 = __ldg(&x[s0 * 64 + 32 + lane]);
            float a1 = __ldg(&x[s1 * 64 + lane]);
            float b1 = __ldg(&x[s1 * 64 + 32 + lane]);
            den  += e0 + e1;
            acc0 += e0 * a0 + e1 * a1;
            acc1 += e0 * b0 + e1 * b1;
        }
        if (i < cnt) {
            unsigned long long p0 = g_cedge[start + i];
            int s0 = (int)(p0 & 0xFFFFFFFFu);
            float e0 = __uint_as_float((unsigned)(p0 >> 32));
            den  += e0;
            acc0 += e0 * __ldg(&x[s0 * 64 + lane]);
            acc1 += e0 * __ldg(&x[s0 * 64 + 32 + lane]);
        }

        // GEMM: h_j = sum_k acc_k * W2[j][k]   (acc = sum ex*x[src])
        float h0 = 0.0f, h1 = 0.0f;
        #pragma unroll
        for (int k = 0; k < 32; k++) {
            float ak = __shfl_sync(0xFFFFFFFFu, acc0, k);
            h0 += ak * w2t[k * 65 + lane];
            h1 += ak * w2t[k * 65 + 32 + lane];
        }
        #pragma unroll
        for (int k = 0; k < 32; k++) {
            float ak = __shfl_sync(0xFFFFFFFFu, acc1, k);
            h0 += ak * w2t[(k + 32) * 65 + lane];
            h1 += ak * w2t[(k + 32) * 65 + 32 + lane];
        }

        float inv = (den > 0.0f) ? (1.0f / den) : 0.0f;
        float a = h0 * inv + bias[lane];
        float b = h1 * inv + bias[lane + 32];

        float sm = a + b;
        #pragma unroll
        for (int off = 16; off; off >>= 1) sm += __shfl_xor_sync(0xFFFFFFFFu, sm, off);
        float mu = sm * (1.0f / 64.0f);

        float da = a - mu, db = b - mu;
        float vs = da * da + db * db;
        #pragma unroll
        for (int off = 16; off; off >>= 1) vs += __shfl_xor_sync(0xFFFFFFFFu, vs, off);
        float rstd = rsqrtf(vs * (1.0f / 64.0f) + 1e-5f);

        out[n * 64 + lane]      = da * rstd * gamma[lane]      + beta[lane];
        out[n * 64 + 32 + lane] = db * rstd * gamma[lane + 32] + beta[lane + 32];
    }
}

// ---------------- launch ----------------
extern "C" void kernel_launch(void* const* d_in, const int* in_sizes, int n_in,
                              void* d_out, int out_size) {
    const float* x         = (const float*)d_in[0];
    const float* edge_attr = (const float*)d_in[1];
    const float* W1        = (const float*)d_in[2];
    const float* W2        = (const float*)d_in[3];
    const float* att_l     = (const float*)d_in[4];
    const float* att_r     = (const float*)d_in[5];
    const float* bias      = (const float*)d_in[6];
    const float* ln_gamma  = (const float*)d_in[7];
    const float* ln_beta   = (const float*)d_in[8];
    const int*   src       = (const int*)d_in[9];
    const int*   dst       = (const int*)d_in[10];
    float* out = (float*)d_out;

    k_u<<<1, 96>>>(W1, att_l);
    k_pre<<<(N_NODES * 32 + 255) / 256, 256>>>(x, att_r);
    k_edgepre<<<(N_EDGES + 255) / 256, 256>>>(edge_attr, src, dst);
    k_scan_a<<<NBLK_SCAN, 256>>>();
    k_scan_b<<<1, 512>>>();
    k_scan_c<<<(N_NODES + 255) / 256, 256>>>();
    k_scatter<<<(N_EDGES + 255) / 256, 256>>>(src, dst);
    k_agg<<<2048, 256>>>(x, W2, bias, ln_gamma, ln_beta, out);
}

// round 3
// speedup vs baseline: 2.2021x; 1.0107x over previous
#include <cuda_runtime.h>
#include <cuda_bf16.h>
#include <math.h>

#define N_NODES 100000
#define N_EDGES 1600000
#define D_IN 64
#define D_OUT 64
#define D_EDGE 16
#define NBLK_SCAN ((N_NODES + 255) / 256)   // 391

// ---------------- scratch (device globals; no allocation) ----------------
__device__ float g_u[80];                         // W1^T @ att_l
__device__ float g_al[N_NODES];                   // x . u[0:64]
__device__ float g_ar[N_NODES];                   // x . att_r
__device__ float g_ex[N_EDGES];                   // exp(leaky(e))
__device__ int   g_cnt[N_NODES];                  // in-degree
__device__ int   g_off[N_NODES];                  // CSR offsets (exclusive scan)
__device__ int   g_cursor[N_NODES];               // scatter cursors
__device__ int   g_bsum[NBLK_SCAN];               // scan block sums
__device__ int   g_bscan[NBLK_SCAN];              // scanned block sums
__device__ unsigned long long g_cedge[N_EDGES];   // packed (ex<<32 | src)

// ---------------- K1: u[c] = sum_o att_l[o] * W1[o][c] ----------------
__global__ void k_u(const float* __restrict__ W1, const float* __restrict__ att_l) {
    int c = threadIdx.x;
    if (c < 80) {
        float acc = 0.0f;
        #pragma unroll
        for (int o = 0; o < D_OUT; o++) acc += att_l[o] * W1[o * 80 + c];
        g_u[c] = acc;
    }
}

// ---------------- K2: warp-per-node al/ar + zero histogram ----------------
__global__ void k_pre(const float* __restrict__ x, const float* __restrict__ att_r) {
    int n = (blockIdx.x * blockDim.x + threadIdx.x) >> 5;
    if (n >= N_NODES) return;
    int lane = threadIdx.x & 31;

    float x0 = x[n * 64 + lane];
    float x1 = x[n * 64 + 32 + lane];
    float pa = x0 * g_u[lane] + x1 * g_u[lane + 32];
    float pr = x0 * att_r[lane] + x1 * att_r[lane + 32];
    #pragma unroll
    for (int off = 16; off; off >>= 1) {
        pa += __shfl_xor_sync(0xFFFFFFFFu, pa, off);
        pr += __shfl_xor_sync(0xFFFFFFFFu, pr, off);
    }
    if (lane == 0) {
        g_al[n] = pa;
        g_ar[n] = pr;
        g_cnt[n] = 0;
    }
}

// ---------------- K3: thread-per-edge score + histogram ----------------
__global__ void k_edgepre(const float* __restrict__ edge_attr,
                          const int* __restrict__ src, const int* __restrict__ dst) {
    __shared__ float su[16];
    if (threadIdx.x < 16) su[threadIdx.x] = g_u[64 + threadIdx.x];
    __syncthreads();

    int e = blockIdx.x * blockDim.x + threadIdx.x;
    if (e >= N_EDGES) return;

    const float4* ea = reinterpret_cast<const float4*>(edge_attr) + e * 4;
    float p = 0.0f;
    #pragma unroll
    for (int q = 0; q < 4; q++) {
        float4 v = __ldg(&ea[q]);
        p += v.x * su[q * 4 + 0] + v.y * su[q * 4 + 1]
           + v.z * su[q * 4 + 2] + v.w * su[q * 4 + 3];
    }
    int s = src[e], d = dst[e];
    float ee = g_al[s] + g_ar[d] + p;
    ee = (ee > 0.0f) ? ee : 0.01f * ee;
    g_ex[e] = __expf(ee);
    atomicAdd(&g_cnt[d], 1);
}

// ---------------- K4a/b/c: exclusive scan of g_cnt -> g_off, g_cursor ----------------
__global__ void k_scan_a() {
    int tid = threadIdx.x, lane = tid & 31, wid = tid >> 5;
    int i = blockIdx.x * 256 + tid;
    int v = (i < N_NODES) ? g_cnt[i] : 0;
    int inc = v;
    #pragma unroll
    for (int d = 1; d < 32; d <<= 1) {
        int t = __shfl_up_sync(0xFFFFFFFFu, inc, d);
        if (lane >= d) inc += t;
    }
    __shared__ int wsum[8];
    if (lane == 31) wsum[wid] = inc;
    __syncthreads();
    if (tid < 8) {
        int w = wsum[tid];
        #pragma unroll
        for (int d = 1; d < 8; d <<= 1) {
            int t = __shfl_up_sync(0xFFu, w, d);
            if (tid >= d) w += t;
        }
        wsum[tid] = w;
    }
    __syncthreads();
    int base = (wid > 0) ? wsum[wid - 1] : 0;
    if (i < N_NODES) g_off[i] = base + inc - v;
    if (tid == 0) g_bsum[blockIdx.x] = wsum[7];
}

__global__ void k_scan_b() {
    int tid = threadIdx.x, lane = tid & 31, wid = tid >> 5;
    int v = (tid < NBLK_SCAN) ? g_bsum[tid] : 0;
    int inc = v;
    #pragma unroll
    for (int d = 1; d < 32; d <<= 1) {
        int t = __shfl_up_sync(0xFFFFFFFFu, inc, d);
        if (lane >= d) inc += t;
    }
    __shared__ int wsum[16];
    if (lane == 31) wsum[wid] = inc;
    __syncthreads();
    if (tid < 16) {
        int w = wsum[tid];
        #pragma unroll
        for (int d = 1; d < 16; d <<= 1) {
            int t = __shfl_up_sync(0xFFFFu, w, d);
            if (tid >= d) w += t;
        }
        wsum[tid] = w;
    }
    __syncthreads();
    int base = (wid > 0) ? wsum[wid - 1] : 0;
    if (tid < NBLK_SCAN) g_bscan[tid] = base + inc - v;
}

__global__ void k_scan_c() {
    int i = blockIdx.x * blockDim.x + threadIdx.x;
    if (i < N_NODES) {
        int o = g_off[i] + g_bscan[i >> 8];
        g_off[i] = o;
        g_cursor[i] = o;
    }
}

// ---------------- K5: scatter packed (ex, src) into CSR ----------------
__global__ void k_scatter(const int* __restrict__ src, const int* __restrict__ dst) {
    int e = blockIdx.x * blockDim.x + threadIdx.x;
    if (e >= N_EDGES) return;
    int d = dst[e];
    int pos = atomicAdd(&g_cursor[d], 1);
    unsigned long long pk =
        ((unsigned long long)__float_as_uint(g_ex[e]) << 32) | (unsigned)src[e];
    g_cedge[pos] = pk;
}

// ---------------- K6: warp-per-dst aggregate (float2 gathers, x4 unroll)
//                     + W2 GEMM + bias + LayerNorm ----------------
__global__ void k_agg(const float* __restrict__ x, const float* __restrict__ W2,
                      const float* __restrict__ bias, const float* __restrict__ gamma,
                      const float* __restrict__ beta, float* __restrict__ out) {
    __shared__ float w2t[64 * 65];   // w2t[k*65+j] = W2[j][k], padded: conflict-free
    int tid = threadIdx.x;
    for (int i = tid; i < 64 * 64; i += 256) {
        int j = i >> 6, k = i & 63;
        w2t[k * 65 + j] = W2[i];
    }
    __syncthreads();

    int lane = tid & 31, wid = tid >> 5;
    const float2* x2 = reinterpret_cast<const float2*>(x);

    for (int n = blockIdx.x * 8 + wid; n < N_NODES; n += gridDim.x * 8) {
        int start = g_off[n];
        int cnt = g_cnt[n];
        float ax = 0.0f, ay = 0.0f, den = 0.0f;   // lane holds dims (2*lane, 2*lane+1)

        int i = 0;
        for (; i + 4 <= cnt; i += 4) {
            unsigned long long p0 = g_cedge[start + i + 0];
            unsigned long long p1 = g_cedge[start + i + 1];
            unsigned long long p2 = g_cedge[start + i + 2];
            unsigned long long p3 = g_cedge[start + i + 3];
            int s0 = (int)(p0 & 0xFFFFFFFFu), s1 = (int)(p1 & 0xFFFFFFFFu);
            int s2 = (int)(p2 & 0xFFFFFFFFu), s3 = (int)(p3 & 0xFFFFFFFFu);
            float e0 = __uint_as_float((unsigned)(p0 >> 32));
            float e1 = __uint_as_float((unsigned)(p1 >> 32));
            float e2 = __uint_as_float((unsigned)(p2 >> 32));
            float e3 = __uint_as_float((unsigned)(p3 >> 32));
            float2 v0 = __ldg(&x2[s0 * 32 + lane]);
            float2 v1 = __ldg(&x2[s1 * 32 + lane]);
            float2 v2 = __ldg(&x2[s2 * 32 + lane]);
            float2 v3 = __ldg(&x2[s3 * 32 + lane]);
            den += (e0 + e1) + (e2 + e3);
            ax += e0 * v0.x + e1 * v1.x + e2 * v2.x + e3 * v3.x;
            ay += e0 * v0.y + e1 * v1.y + e2 * v2.y + e3 * v3.y;
        }
        for (; i < cnt; i++) {
            unsigned long long p0 = g_cedge[start + i];
            int s0 = (int)(p0 & 0xFFFFFFFFu);
            float e0 = __uint_as_float((unsigned)(p0 >> 32));
            float2 v0 = __ldg(&x2[s0 * 32 + lane]);
            den += e0;
            ax += e0 * v0.x;
            ay += e0 * v0.y;
        }

        // GEMM: h_j = sum_k A_k * W2[j][k], A_{2q}=shfl(ax,q), A_{2q+1}=shfl(ay,q)
        float h0 = 0.0f, h1 = 0.0f;
        #pragma unroll
        for (int q = 0; q < 32; q++) {
            float aq = __shfl_sync(0xFFFFFFFFu, ax, q);
            float bq = __shfl_sync(0xFFFFFFFFu, ay, q);
            h0 += aq * w2t[(2 * q) * 65 + lane]      + bq * w2t[(2 * q + 1) * 65 + lane];
            h1 += aq * w2t[(2 * q) * 65 + 32 + lane] + bq * w2t[(2 * q + 1) * 65 + 32 + lane];
        }

        float inv = (den > 0.0f) ? (1.0f / den) : 0.0f;
        float a = h0 * inv + bias[lane];
        float b = h1 * inv + bias[lane + 32];

        float sm = a + b;
        #pragma unroll
        for (int off = 16; off; off >>= 1) sm += __shfl_xor_sync(0xFFFFFFFFu, sm, off);
        float mu = sm * (1.0f / 64.0f);

        float da = a - mu, db = b - mu;
        float vs = da * da + db * db;
        #pragma unroll
        for (int off = 16; off; off >>= 1) vs += __shfl_xor_sync(0xFFFFFFFFu, vs, off);
        float rstd = rsqrtf(vs * (1.0f / 64.0f) + 1e-5f);

        out[n * 64 + lane]      = da * rstd * gamma[lane]      + beta[lane];
        out[n * 64 + 32 + lane] = db * rstd * gamma[lane + 32] + beta[lane + 32];
    }
}

// ---------------- launch ----------------
extern "C" void kernel_launch(void* const* d_in, const int* in_sizes, int n_in,
                              void* d_out, int out_size) {
    const float* x         = (const float*)d_in[0];
    const float* edge_attr = (const float*)d_in[1];
    const float* W1        = (const float*)d_in[2];
    const float* W2        = (const float*)d_in[3];
    const float* att_l     = (const float*)d_in[4];
    const float* att_r     = (const float*)d_in[5];
    const float* bias      = (const float*)d_in[6];
    const float* ln_gamma  = (const float*)d_in[7];
    const float* ln_beta   = (const float*)d_in[8];
    const int*   src       = (const int*)d_in[9];
    const int*   dst       = (const int*)d_in[10];
    float* out = (float*)d_out;

    k_u<<<1, 96>>>(W1, att_l);
    k_pre<<<(N_NODES * 32 + 255) / 256, 256>>>(x, att_r);
    k_edgepre<<<(N_EDGES + 255) / 256, 256>>>(edge_attr, src, dst);
    k_scan_a<<<NBLK_SCAN, 256>>>();
    k_scan_b<<<1, 512>>>();
    k_scan_c<<<(N_NODES + 255) / 256, 256>>>();
    k_scatter<<<(N_EDGES + 255) / 256, 256>>>(src, dst);
    k_agg<<<2048, 256>>>(x, W2, bias, ln_gamma, ln_beta, out);
}

// round 4
// speedup vs baseline: 2.2949x; 1.0422x over previous
#include <cuda_runtime.h>
#include <cuda_fp16.h>
#include <math.h>

#define N_NODES 100000
#define N_EDGES 1600000
#define D_IN 64
#define D_OUT 64
#define D_EDGE 16
#define NBLK_SCAN ((N_NODES + 255) / 256)   // 391

// ---------------- scratch (device globals; no allocation) ----------------
__device__ float g_u[80];                         // W1^T @ att_l
__device__ float g_al[N_NODES];                   // x . u[0:64]
__device__ float g_ar[N_NODES];                   // x . att_r
__device__ __half2 g_xh[N_NODES * 32];            // x rows in half2 (lane l -> dims 2l,2l+1)
__device__ int   g_cnt[N_NODES];                  // in-degree
__device__ int   g_off[N_NODES];                  // CSR offsets (exclusive scan)
__device__ int   g_cursor[N_NODES];               // scatter cursors
__device__ int   g_bsum[NBLK_SCAN];               // scan block sums
__device__ int   g_bscan[NBLK_SCAN];              // scanned block sums
__device__ unsigned long long g_cedge[N_EDGES];   // packed (ex<<32 | src)

// ---------------- K1: u[c] = sum_o att_l[o] * W1[o][c] ----------------
__global__ void k_u(const float* __restrict__ W1, const float* __restrict__ att_l) {
    int c = threadIdx.x;
    if (c < 80) {
        float acc = 0.0f;
        #pragma unroll
        for (int o = 0; o < D_OUT; o++) acc += att_l[o] * W1[o * 80 + c];
        g_u[c] = acc;
    }
}

// ---------------- K2: warp-per-node al/ar + half2 conversion + zero cnt ----------------
__global__ void k_pre(const float* __restrict__ x, const float* __restrict__ att_r) {
    int n = (blockIdx.x * blockDim.x + threadIdx.x) >> 5;
    if (n >= N_NODES) return;
    int lane = threadIdx.x & 31;

    float2 v = __ldg(reinterpret_cast<const float2*>(x) + n * 32 + lane);
    g_xh[n * 32 + lane] = __floats2half2_rn(v.x, v.y);

    float pa = v.x * g_u[2 * lane] + v.y * g_u[2 * lane + 1];
    float pr = v.x * att_r[2 * lane] + v.y * att_r[2 * lane + 1];
    #pragma unroll
    for (int off = 16; off; off >>= 1) {
        pa += __shfl_xor_sync(0xFFFFFFFFu, pa, off);
        pr += __shfl_xor_sync(0xFFFFFFFFu, pr, off);
    }
    if (lane == 0) {
        g_al[n] = pa;
        g_ar[n] = pr;
        g_cnt[n] = 0;
    }
}

// ---------------- K3: histogram of dst ----------------
__global__ void k_count(const int* __restrict__ dst) {
    int e = blockIdx.x * blockDim.x + threadIdx.x;
    if (e < N_EDGES) atomicAdd(&g_cnt[dst[e]], 1);
}

// ---------------- K4a/b/c: exclusive scan of g_cnt -> g_off, g_cursor ----------------
__global__ void k_scan_a() {
    int tid = threadIdx.x, lane = tid & 31, wid = tid >> 5;
    int i = blockIdx.x * 256 + tid;
    int v = (i < N_NODES) ? g_cnt[i] : 0;
    int inc = v;
    #pragma unroll
    for (int d = 1; d < 32; d <<= 1) {
        int t = __shfl_up_sync(0xFFFFFFFFu, inc, d);
        if (lane >= d) inc += t;
    }
    __shared__ int wsum[8];
    if (lane == 31) wsum[wid] = inc;
    __syncthreads();
    if (tid < 8) {
        int w = wsum[tid];
        #pragma unroll
        for (int d = 1; d < 8; d <<= 1) {
            int t = __shfl_up_sync(0xFFu, w, d);
            if (tid >= d) w += t;
        }
        wsum[tid] = w;
    }
    __syncthreads();
    int base = (wid > 0) ? wsum[wid - 1] : 0;
    if (i < N_NODES) g_off[i] = base + inc - v;
    if (tid == 0) g_bsum[blockIdx.x] = wsum[7];
}

__global__ void k_scan_b() {
    int tid = threadIdx.x, lane = tid & 31, wid = tid >> 5;
    int v = (tid < NBLK_SCAN) ? g_bsum[tid] : 0;
    int inc = v;
    #pragma unroll
    for (int d = 1; d < 32; d <<= 1) {
        int t = __shfl_up_sync(0xFFFFFFFFu, inc, d);
        if (lane >= d) inc += t;
    }
    __shared__ int wsum[16];
    if (lane == 31) wsum[wid] = inc;
    __syncthreads();
    if (tid < 16) {
        int w = wsum[tid];
        #pragma unroll
        for (int d = 1; d < 16; d <<= 1) {
            int t = __shfl_up_sync(0xFFFFu, w, d);
            if (tid >= d) w += t;
        }
        wsum[tid] = w;
    }
    __syncthreads();
    int base = (wid > 0) ? wsum[wid - 1] : 0;
    if (tid < NBLK_SCAN) g_bscan[tid] = base + inc - v;
}

__global__ void k_scan_c() {
    int i = blockIdx.x * blockDim.x + threadIdx.x;
    if (i < N_NODES) {
        int o = g_off[i] + g_bscan[i >> 8];
        g_off[i] = o;
        g_cursor[i] = o;
    }
}

// ---------------- K5: fused edge score + direct CSR scatter ----------------
__global__ void k_edge(const float* __restrict__ edge_attr,
                       const int* __restrict__ src, const int* __restrict__ dst) {
    __shared__ float su[16];
    if (threadIdx.x < 16) su[threadIdx.x] = g_u[64 + threadIdx.x];
    __syncthreads();

    int e = blockIdx.x * blockDim.x + threadIdx.x;
    if (e >= N_EDGES) return;

    const float4* ea = reinterpret_cast<const float4*>(edge_attr) + e * 4;
    float p = 0.0f;
    #pragma unroll
    for (int q = 0; q < 4; q++) {
        float4 v = __ldg(&ea[q]);
        p += v.x * su[q * 4 + 0] + v.y * su[q * 4 + 1]
           + v.z * su[q * 4 + 2] + v.w * su[q * 4 + 3];
    }
    int s = src[e], d = dst[e];
    float ee = g_al[s] + g_ar[d] + p;
    ee = (ee > 0.0f) ? ee : 0.01f * ee;
    float ex = __expf(ee);

    int pos = atomicAdd(&g_cursor[d], 1);
    g_cedge[pos] =
        ((unsigned long long)__float_as_uint(ex) << 32) | (unsigned)s;
}

// ---------------- K6: warp-per-dst aggregate (half2 gathers, x4 unroll)
//                     + W2 GEMM + bias + LayerNorm ----------------
__global__ void k_agg(const float* __restrict__ W2,
                      const float* __restrict__ bias, const float* __restrict__ gamma,
                      const float* __restrict__ beta, float* __restrict__ out) {
    __shared__ float w2t[64 * 65];   // w2t[k*65+j] = W2[j][k], padded: conflict-free
    int tid = threadIdx.x;
    for (int i = tid; i < 64 * 64; i += 256) {
        int j = i >> 6, k = i & 63;
        w2t[k * 65 + j] = W2[i];
    }
    __syncthreads();

    int lane = tid & 31, wid = tid >> 5;

    for (int n = blockIdx.x * 8 + wid; n < N_NODES; n += gridDim.x * 8) {
        int start = g_off[n];
        int cnt = g_cnt[n];
        float ax = 0.0f, ay = 0.0f, den = 0.0f;   // lane holds dims (2*lane, 2*lane+1)

        int i = 0;
        for (; i + 4 <= cnt; i += 4) {
            unsigned long long p0 = g_cedge[start + i + 0];
            unsigned long long p1 = g_cedge[start + i + 1];
            unsigned long long p2 = g_cedge[start + i + 2];
            unsigned long long p3 = g_cedge[start + i + 3];
            int s0 = (int)(p0 & 0xFFFFFFFFu), s1 = (int)(p1 & 0xFFFFFFFFu);
            int s2 = (int)(p2 & 0xFFFFFFFFu), s3 = (int)(p3 & 0xFFFFFFFFu);
            float e0 = __uint_as_float((unsigned)(p0 >> 32));
            float e1 = __uint_as_float((unsigned)(p1 >> 32));
            float e2 = __uint_as_float((unsigned)(p2 >> 32));
            float e3 = __uint_as_float((unsigned)(p3 >> 32));
            float2 v0 = __half22float2(__ldg(&g_xh[s0 * 32 + lane]));
            float2 v1 = __half22float2(__ldg(&g_xh[s1 * 32 + lane]));
            float2 v2 = __half22float2(__ldg(&g_xh[s2 * 32 + lane]));
            float2 v3 = __half22float2(__ldg(&g_xh[s3 * 32 + lane]));
            den += (e0 + e1) + (e2 + e3);
            ax += e0 * v0.x + e1 * v1.x + e2 * v2.x + e3 * v3.x;
            ay += e0 * v0.y + e1 * v1.y + e2 * v2.y + e3 * v3.y;
        }
        for (; i < cnt; i++) {
            unsigned long long p0 = g_cedge[start + i];
            int s0 = (int)(p0 & 0xFFFFFFFFu);
            float e0 = __uint_as_float((unsigned)(p0 >> 32));
            float2 v0 = __half22float2(__ldg(&g_xh[s0 * 32 + lane]));
            den += e0;
            ax += e0 * v0.x;
            ay += e0 * v0.y;
        }

        // GEMM: h_j = sum_k A_k * W2[j][k], A_{2q}=shfl(ax,q), A_{2q+1}=shfl(ay,q)
        float h0 = 0.0f, h1 = 0.0f;
        #pragma unroll
        for (int q = 0; q < 32; q++) {
            float aq = __shfl_sync(0xFFFFFFFFu, ax, q);
            float bq = __shfl_sync(0xFFFFFFFFu, ay, q);
            h0 += aq * w2t[(2 * q) * 65 + lane]      + bq * w2t[(2 * q + 1) * 65 + lane];
            h1 += aq * w2t[(2 * q) * 65 + 32 + lane] + bq * w2t[(2 * q + 1) * 65 + 32 + lane];
        }

        float inv = (den > 0.0f) ? (1.0f / den) : 0.0f;
        float a = h0 * inv + bias[lane];
        float b = h1 * inv + bias[lane + 32];

        float sm = a + b;
        #pragma unroll
        for (int off = 16; off; off >>= 1) sm += __shfl_xor_sync(0xFFFFFFFFu, sm, off);
        float mu = sm * (1.0f / 64.0f);

        float da = a - mu, db = b - mu;
        float vs = da * da + db * db;
        #pragma unroll
        for (int off = 16; off; off >>= 1) vs += __shfl_xor_sync(0xFFFFFFFFu, vs, off);
        float rstd = rsqrtf(vs * (1.0f / 64.0f) + 1e-5f);

        out[n * 64 + lane]      = da * rstd * gamma[lane]      + beta[lane];
        out[n * 64 + 32 + lane] = db * rstd * gamma[lane + 32] + beta[lane + 32];
    }
}

// ---------------- launch ----------------
extern "C" void kernel_launch(void* const* d_in, const int* in_sizes, int n_in,
                              void* d_out, int out_size) {
    const float* x         = (const float*)d_in[0];
    const float* edge_attr = (const float*)d_in[1];
    const float* W1        = (const float*)d_in[2];
    const float* W2        = (const float*)d_in[3];
    const float* att_l     = (const float*)d_in[4];
    const float* att_r     = (const float*)d_in[5];
    const float* bias      = (const float*)d_in[6];
    const float* ln_gamma  = (const float*)d_in[7];
    const float* ln_beta   = (const float*)d_in[8];
    const int*   src       = (const int*)d_in[9];
    const int*   dst       = (const int*)d_in[10];
    float* out = (float*)d_out;

    k_u<<<1, 96>>>(W1, att_l);
    k_pre<<<(N_NODES * 32 + 255) / 256, 256>>>(x, att_r);
    k_count<<<(N_EDGES + 255) / 256, 256>>>(dst);
    k_scan_a<<<NBLK_SCAN, 256>>>();
    k_scan_b<<<1, 512>>>();
    k_scan_c<<<(N_NODES + 255) / 256, 256>>>();
    k_edge<<<(N_EDGES + 255) / 256, 256>>>(edge_attr, src, dst);
    k_agg<<<2048, 256>>>(W2, bias, ln_gamma, ln_beta, out);
}